// round 1
// baseline (speedup 1.0000x reference)
#include <cuda_runtime.h>
#include <math.h>

#define NB 2
#define NS 2048
#define ND 1024
#define NH 16
#define HD 64
#define BHN (NB*NH)            // 32
#define NTOK (NB*NS)           // 4096
#define OUT_ELEMS (NB*NS*ND)   // 4194304

// ---------------- scratch (device globals, allocation-free) ----------------
__device__ float g_q[BHN*NS*HD];
__device__ float g_k[BHN*NS*HD];
__device__ float g_v[BHN*NS*HD];
__device__ float g_oh[BHN*NS*HD];
__device__ float g_sq[BHN*NS];
__device__ float g_d2c[BHN*NS];
__device__ float g_mmd[BHN*NS];
__device__ float g_tls[BHN*NS];
__device__ float g_rm[BHN*NS];
__device__ float g_rl[BHN*NS];
__device__ float g_d2cmax[BHN];
__device__ unsigned char g_land[BHN*NS];

// ---------------- K1: QKV GEMM  Y = x @ W^T + b, scatter to q/k/v ----------
__global__ void __launch_bounds__(256) k_qkv(const float* __restrict__ x,
                                             const float* __restrict__ w,
                                             const float* __restrict__ bias)
{
    __shared__ float Xs[64][33];
    __shared__ float Ws[64][33];
    const int tid = threadIdx.x;
    const int tx = tid & 15, ty = tid >> 4;
    const int n0 = blockIdx.y * 64;
    const int m0 = blockIdx.x * 64;
    float acc[4][4];
    #pragma unroll
    for (int i = 0; i < 4; i++)
        #pragma unroll
        for (int j = 0; j < 4; j++) acc[i][j] = 0.f;

    for (int k0 = 0; k0 < ND; k0 += 32) {
        #pragma unroll
        for (int q = 0; q < 2; q++) {
            int f4  = tid * 2 + q;            // 0..511
            int row = f4 >> 3;
            int col = (f4 & 7) * 4;
            float4 xv = *reinterpret_cast<const float4*>(&x[(size_t)(n0 + row) * ND + k0 + col]);
            Xs[row][col + 0] = xv.x; Xs[row][col + 1] = xv.y;
            Xs[row][col + 2] = xv.z; Xs[row][col + 3] = xv.w;
            float4 wv = *reinterpret_cast<const float4*>(&w[(size_t)(m0 + row) * ND + k0 + col]);
            Ws[row][col + 0] = wv.x; Ws[row][col + 1] = wv.y;
            Ws[row][col + 2] = wv.z; Ws[row][col + 3] = wv.w;
        }
        __syncthreads();
        #pragma unroll
        for (int kk = 0; kk < 32; kk++) {
            float a[4], b[4];
            #pragma unroll
            for (int i = 0; i < 4; i++) a[i] = Xs[ty * 4 + i][kk];
            #pragma unroll
            for (int j = 0; j < 4; j++) b[j] = Ws[tx * 4 + j][kk];
            #pragma unroll
            for (int i = 0; i < 4; i++)
                #pragma unroll
                for (int j = 0; j < 4; j++) acc[i][j] += a[i] * b[j];
        }
        __syncthreads();
    }

    const int which = m0 >> 10;              // 0:q 1:k 2:v
    const int h = (m0 & 1023) >> 6;
    float* dst = (which == 0) ? g_q : (which == 1) ? g_k : g_v;
    #pragma unroll
    for (int i = 0; i < 4; i++) {
        int n = n0 + ty * 4 + i;
        int b = n >> 11, s = n & 2047;
        size_t base = ((size_t)(b * NH + h) * NS + s) * HD;
        #pragma unroll
        for (int j = 0; j < 4; j++) {
            int d = tx * 4 + j;
            dst[base + d] = acc[i][j] + bias[m0 + d];
        }
    }
}

// ---------------- K2: per-(b,h) centroid, sq-norm, dist-to-centroid --------
__global__ void __launch_bounds__(256) k_stats(const float* __restrict__ x)
{
    const int bh = blockIdx.x;
    const int b = bh >> 4, h = bh & 15;
    const int tid = threadIdx.x;
    __shared__ float cent[HD];
    __shared__ float red[256];

    {   // centroid
        int g = tid >> 6;
        int d = tid & 63;
        float s = 0.f;
        for (int t = g; t < NS; t += 4)
            s += x[(size_t)(b * NS + t) * ND + h * HD + d];
        red[tid] = s;
        __syncthreads();
        if (tid < 64)
            cent[tid] = (red[tid] + red[tid + 64] + red[tid + 128] + red[tid + 192]) * (1.0f / NS);
        __syncthreads();
    }

    float lmax = 0.f;
    for (int t = tid; t < NS; t += 256) {
        const float* row = &x[(size_t)(b * NS + t) * ND + h * HD];
        float sq = 0.f, dc = 0.f;
        #pragma unroll
        for (int d = 0; d < HD; d++) {
            float v = row[d];
            sq += v * v;
            float dd = v - cent[d];
            dc += dd * dd;
        }
        dc = sqrtf(dc);
        g_sq[bh * NS + t] = sq;
        g_d2c[bh * NS + t] = dc;
        lmax = fmaxf(lmax, dc);
    }
    red[tid] = lmax;
    __syncthreads();
    for (int s2 = 128; s2 > 0; s2 >>= 1) {
        if (tid < s2) red[tid] = fmaxf(red[tid], red[tid + s2]);
        __syncthreads();
    }
    if (tid == 0) g_d2cmax[bh] = red[0];
}

// ---------------- K3: 10-NN distance (mean-min-dist surrogate) -------------
__global__ void __launch_bounds__(128) k_knn(const float* __restrict__ x)
{
    const int bh = blockIdx.y;
    const int b = bh >> 4, h = bh & 15;
    const int s = blockIdx.x * 128 + threadIdx.x;
    const int tid = threadIdx.x;
    __shared__ float Ks[64][HD + 1];
    __shared__ float sqs[64];

    float rv[HD];
    #pragma unroll
    for (int d = 0; d < HD; d++)
        rv[d] = x[(size_t)(b * NS + s) * ND + h * HD + d];
    const float mysq = g_sq[bh * NS + s];

    float best[10];
    #pragma unroll
    for (int i = 0; i < 10; i++) best[i] = 3.0e38f;

    for (int t0 = 0; t0 < NS; t0 += 64) {
        #pragma unroll
        for (int q = 0; q < 8; q++) {
            int f4  = tid + 128 * q;         // 0..1023
            int row = f4 >> 4;
            int col = (f4 & 15) * 4;
            float4 v = *reinterpret_cast<const float4*>(&x[(size_t)(b * NS + t0 + row) * ND + h * HD + col]);
            Ks[row][col + 0] = v.x; Ks[row][col + 1] = v.y;
            Ks[row][col + 2] = v.z; Ks[row][col + 3] = v.w;
        }
        if (tid < 64) sqs[tid] = g_sq[bh * NS + t0 + tid];
        __syncthreads();

        for (int t = 0; t < 64; t++) {
            float dot = 0.f;
            #pragma unroll
            for (int d = 0; d < HD; d++) dot += rv[d] * Ks[t][d];
            float d2 = mysq + sqs[t] - 2.0f * dot;
            if (d2 < best[9]) {
                float v = d2;
                #pragma unroll
                for (int i = 0; i < 10; i++) {
                    if (v < best[i]) { float tmp = best[i]; best[i] = v; v = tmp; }
                }
            }
        }
        __syncthreads();
    }
    g_mmd[bh * NS + s] = sqrtf(fmaxf(best[9], 0.f));
}

// ---------------- K4: tls = a*lifetime + (1-a)*mmd_norm --------------------
__global__ void __launch_bounds__(256) k_tls()
{
    const int bh = blockIdx.x;
    const int tid = threadIdx.x;
    __shared__ float red[256];
    float lmax = 0.f;
    for (int t = tid; t < NS; t += 256) lmax = fmaxf(lmax, g_mmd[bh * NS + t]);
    red[tid] = lmax;
    __syncthreads();
    for (int s2 = 128; s2 > 0; s2 >>= 1) {
        if (tid < s2) red[tid] = fmaxf(red[tid], red[tid + s2]);
        __syncthreads();
    }
    const float mmax = red[0];
    const float dmax = g_d2cmax[bh];
    for (int t = tid; t < NS; t += 256) {
        float life = g_d2c[bh * NS + t] / (dmax + 1e-8f);
        float mn   = g_mmd[bh * NS + t] / (mmax + 1e-8f);
        g_tls[bh * NS + t] = 0.7f * life + 0.3f * mn;
    }
}

// ---------------- K5: top-675 selection via bitonic sort -------------------
__global__ void __launch_bounds__(1024) k_topk()
{
    const int bh = blockIdx.x;
    const int tid = threadIdx.x;
    __shared__ unsigned long long key[NS];

    for (int i = tid; i < NS; i += 1024) {
        float v = g_tls[bh * NS + i];
        unsigned int u = __float_as_uint(v);
        u = (u & 0x80000000u) ? ~u : (u | 0x80000000u);   // order-preserving map
        key[i] = ((unsigned long long)u << 32) | (unsigned int)(~(unsigned int)i);
    }
    for (int i = tid; i < NS; i += 1024) g_land[bh * NS + i] = 0;
    __syncthreads();

    // bitonic sort, descending (value desc; ties -> smaller index first)
    for (int k = 2; k <= NS; k <<= 1) {
        for (int j = k >> 1; j > 0; j >>= 1) {
            for (int i = tid; i < NS; i += 1024) {
                int ixj = i ^ j;
                if (ixj > i) {
                    unsigned long long a = key[i], b = key[ixj];
                    bool swap = ((i & k) == 0) ? (a < b) : (a > b);
                    if (swap) { key[i] = b; key[ixj] = a; }
                }
            }
            __syncthreads();
        }
    }
    // n_keep = max(int(2048*0.33), 2) = 675
    if (tid < 675) {
        unsigned int idx = ~(unsigned int)(key[tid] & 0xFFFFFFFFu);
        g_land[bh * NS + idx] = 1;
    }
}

// ---------------- K6: masked scores + online softmax stats -----------------
__global__ void __launch_bounds__(256) k_scores(float* __restrict__ attn)
{
    const int bh = blockIdx.y;
    const int q0 = blockIdx.x * 64;
    const int tid = threadIdx.x;
    const int tx = tid & 15, ty = tid >> 4;
    __shared__ float Qs[64][65];
    __shared__ float Ks[64][65];
    __shared__ unsigned char lnd[64];
    __shared__ float Ms[64][17];
    __shared__ float Ls[64][17];

    #pragma unroll
    for (int q = 0; q < 4; q++) {
        int f4  = tid + 256 * q;            // 0..1023
        int row = f4 >> 4;
        int col = (f4 & 15) * 4;
        float4 v = *reinterpret_cast<const float4*>(&g_q[((size_t)bh * NS + q0 + row) * HD + col]);
        Qs[row][col + 0] = v.x; Qs[row][col + 1] = v.y;
        Qs[row][col + 2] = v.z; Qs[row][col + 3] = v.w;
    }

    float rm[4], rl[4];
    #pragma unroll
    for (int i = 0; i < 4; i++) { rm[i] = -3.0e38f; rl[i] = 0.f; }

    for (int t0 = 0; t0 < NS; t0 += 64) {
        #pragma unroll
        for (int q = 0; q < 4; q++) {
            int f4  = tid + 256 * q;
            int row = f4 >> 4;
            int col = (f4 & 15) * 4;
            float4 v = *reinterpret_cast<const float4*>(&g_k[((size_t)bh * NS + t0 + row) * HD + col]);
            Ks[row][col + 0] = v.x; Ks[row][col + 1] = v.y;
            Ks[row][col + 2] = v.z; Ks[row][col + 3] = v.w;
        }
        if (tid < 64) lnd[tid] = g_land[bh * NS + t0 + tid];
        __syncthreads();

        float acc[4][4];
        #pragma unroll
        for (int i = 0; i < 4; i++)
            #pragma unroll
            for (int j = 0; j < 4; j++) acc[i][j] = 0.f;
        #pragma unroll
        for (int d = 0; d < HD; d++) {
            float a[4], b[4];
            #pragma unroll
            for (int i = 0; i < 4; i++) a[i] = Qs[ty * 4 + i][d];
            #pragma unroll
            for (int j = 0; j < 4; j++) b[j] = Ks[tx * 4 + j][d];
            #pragma unroll
            for (int i = 0; i < 4; i++)
                #pragma unroll
                for (int j = 0; j < 4; j++) acc[i][j] += a[i] * b[j];
        }

        #pragma unroll
        for (int i = 0; i < 4; i++) {
            int row = q0 + ty * 4 + i;
            float vals[4];
            #pragma unroll
            for (int j = 0; j < 4; j++) {
                int col = t0 + tx * 4 + j;
                float sc = acc[i][j] * 0.125f;
                int rel = col - row;
                bool keep = (rel >= -64 && rel <= 64) || (lnd[tx * 4 + j] != 0);
                vals[j] = keep ? sc : -10000.0f;
            }
            *reinterpret_cast<float4*>(&attn[((size_t)bh * NS + row) * NS + t0 + tx * 4]) =
                make_float4(vals[0], vals[1], vals[2], vals[3]);
            float tm = fmaxf(fmaxf(vals[0], vals[1]), fmaxf(vals[2], vals[3]));
            float nm = fmaxf(rm[i], tm);
            float sum = expf(vals[0] - nm) + expf(vals[1] - nm)
                      + expf(vals[2] - nm) + expf(vals[3] - nm);
            rl[i] = rl[i] * expf(rm[i] - nm) + sum;
            rm[i] = nm;
        }
        __syncthreads();
    }

    #pragma unroll
    for (int i = 0; i < 4; i++) { Ms[ty * 4 + i][tx] = rm[i]; Ls[ty * 4 + i][tx] = rl[i]; }
    __syncthreads();
    if (tid < 64) {
        float m = -3.0e38f;
        #pragma unroll
        for (int t = 0; t < 16; t++) m = fmaxf(m, Ms[tid][t]);
        float l = 0.f;
        #pragma unroll
        for (int t = 0; t < 16; t++) l += Ls[tid][t] * expf(Ms[tid][t] - m);
        g_rm[bh * NS + q0 + tid] = m;
        g_rl[bh * NS + q0 + tid] = l;
    }
}

// ---------------- K7: normalize attn in place + out_h = attn @ v -----------
__global__ void __launch_bounds__(256) k_av(float* __restrict__ attn)
{
    const int bh = blockIdx.y;
    const int q0 = blockIdx.x * 64;
    const int tid = threadIdx.x;
    const int tx = tid & 15, ty = tid >> 4;
    __shared__ float Ps[64][65];
    __shared__ float Vs[64][65];
    __shared__ float sm[64], sinv[64];

    if (tid < 64) {
        sm[tid]   = g_rm[bh * NS + q0 + tid];
        sinv[tid] = 1.0f / g_rl[bh * NS + q0 + tid];
    }
    __syncthreads();

    float acc[4][4];
    #pragma unroll
    for (int i = 0; i < 4; i++)
        #pragma unroll
        for (int j = 0; j < 4; j++) acc[i][j] = 0.f;

    for (int t0 = 0; t0 < NS; t0 += 64) {
        #pragma unroll
        for (int q = 0; q < 4; q++) {
            int f4  = tid + 256 * q;
            int row = f4 >> 4;
            int col = (f4 & 15) * 4;
            size_t aoff = ((size_t)bh * NS + q0 + row) * NS + t0 + col;
            float4 v = *reinterpret_cast<const float4*>(&attn[aoff]);
            float m = sm[row], iv = sinv[row];
            float4 p;
            p.x = expf(v.x - m) * iv;
            p.y = expf(v.y - m) * iv;
            p.z = expf(v.z - m) * iv;
            p.w = expf(v.w - m) * iv;
            *reinterpret_cast<float4*>(&attn[aoff]) = p;
            Ps[row][col + 0] = p.x; Ps[row][col + 1] = p.y;
            Ps[row][col + 2] = p.z; Ps[row][col + 3] = p.w;
            float4 vv = *reinterpret_cast<const float4*>(&g_v[((size_t)bh * NS + t0 + row) * HD + col]);
            Vs[row][col + 0] = vv.x; Vs[row][col + 1] = vv.y;
            Vs[row][col + 2] = vv.z; Vs[row][col + 3] = vv.w;
        }
        __syncthreads();
        #pragma unroll
        for (int t = 0; t < 64; t++) {
            float a[4], b[4];
            #pragma unroll
            for (int i = 0; i < 4; i++) a[i] = Ps[ty * 4 + i][t];
            #pragma unroll
            for (int j = 0; j < 4; j++) b[j] = Vs[t][tx * 4 + j];
            #pragma unroll
            for (int i = 0; i < 4; i++)
                #pragma unroll
                for (int j = 0; j < 4; j++) acc[i][j] += a[i] * b[j];
        }
        __syncthreads();
    }

    #pragma unroll
    for (int i = 0; i < 4; i++)
        #pragma unroll
        for (int j = 0; j < 4; j++)
            g_oh[((size_t)bh * NS + q0 + ty * 4 + i) * HD + tx * 4 + j] = acc[i][j];
}

// ---------------- K8: out = concat_heads(out_h) @ out_w^T + b --------------
__global__ void __launch_bounds__(256) k_proj(const float* __restrict__ w,
                                              const float* __restrict__ bias,
                                              float* __restrict__ out)
{
    __shared__ float Xs[64][33];
    __shared__ float Ws[64][33];
    const int tid = threadIdx.x;
    const int tx = tid & 15, ty = tid >> 4;
    const int n0 = blockIdx.y * 64;
    const int m0 = blockIdx.x * 64;
    float acc[4][4];
    #pragma unroll
    for (int i = 0; i < 4; i++)
        #pragma unroll
        for (int j = 0; j < 4; j++) acc[i][j] = 0.f;

    for (int k0 = 0; k0 < ND; k0 += 32) {
        const int h = k0 >> 6;
        const int dbase = k0 & 63;
        #pragma unroll
        for (int q = 0; q < 2; q++) {
            int f4  = tid * 2 + q;
            int row = f4 >> 3;
            int col = (f4 & 7) * 4;
            int n = n0 + row;
            int b = n >> 11, s = n & 2047;
            float4 xv = *reinterpret_cast<const float4*>(
                &g_oh[((size_t)(b * NH + h) * NS + s) * HD + dbase + col]);
            Xs[row][col + 0] = xv.x; Xs[row][col + 1] = xv.y;
            Xs[row][col + 2] = xv.z; Xs[row][col + 3] = xv.w;
            float4 wv = *reinterpret_cast<const float4*>(&w[(size_t)(m0 + row) * ND + k0 + col]);
            Ws[row][col + 0] = wv.x; Ws[row][col + 1] = wv.y;
            Ws[row][col + 2] = wv.z; Ws[row][col + 3] = wv.w;
        }
        __syncthreads();
        #pragma unroll
        for (int kk = 0; kk < 32; kk++) {
            float a[4], b[4];
            #pragma unroll
            for (int i = 0; i < 4; i++) a[i] = Xs[ty * 4 + i][kk];
            #pragma unroll
            for (int j = 0; j < 4; j++) b[j] = Ws[tx * 4 + j][kk];
            #pragma unroll
            for (int i = 0; i < 4; i++)
                #pragma unroll
                for (int j = 0; j < 4; j++) acc[i][j] += a[i] * b[j];
        }
        __syncthreads();
    }

    #pragma unroll
    for (int i = 0; i < 4; i++)
        #pragma unroll
        for (int j = 0; j < 4; j++)
            out[(size_t)(n0 + ty * 4 + i) * ND + m0 + tx * 4 + j] =
                acc[i][j] + bias[m0 + tx * 4 + j];
}

// ---------------------------------------------------------------------------
extern "C" void kernel_launch(void* const* d_in, const int* in_sizes, int n_in,
                              void* d_out, int out_size)
{
    const float* x     = (const float*)d_in[0];
    const float* qkv_w = (const float*)d_in[1];
    const float* qkv_b = (const float*)d_in[2];
    const float* out_w = (const float*)d_in[3];
    const float* out_b = (const float*)d_in[4];
    float* out  = (float*)d_out;
    float* attn = out + OUT_ELEMS;   // (out, attn) concatenated in d_out

    k_qkv  <<<dim3(48, 64), 256>>>(x, qkv_w, qkv_b);
    k_stats<<<32, 256>>>(x);
    k_knn  <<<dim3(16, 32), 128>>>(x);
    k_tls  <<<32, 256>>>();
    k_topk <<<32, 1024>>>();
    k_scores<<<dim3(32, 32), 256>>>(attn);
    k_av   <<<dim3(32, 32), 256>>>(attn);
    k_proj <<<dim3(16, 64), 256>>>(out_w, out_b, out);
}